// round 9
// baseline (speedup 1.0000x reference)
#include <cuda_runtime.h>
#include <cstdint>

#define N_MAX 100000
#define E_MAX 1200000
#define D 64

__device__ __align__(16) int   g_deg [N_MAX];
__device__ __align__(16) float g_dinv[N_MAX];
__device__ __align__(16) int   g_off [N_MAX];   // CSR start
__device__ __align__(16) int   g_cur [N_MAX];   // fill cursor -> CSR end
__device__ __align__(16) int   g_csr [E_MAX];   // src ids bucketed by dst
__device__ __align__(16) float g_hs  [N_MAX * D];
__device__ __align__(16) float g_x2  [N_MAX * D];

// ---------------- degree ----------------

__global__ void k_init_deg(int n) {
    int i = blockIdx.x * blockDim.x + threadIdx.x;
    if (i < n) g_deg[i] = 1;                 // self-loop
}

__global__ void k_count(const int* __restrict__ ei, int E) {
    int e = blockIdx.x * blockDim.x + threadIdx.x;
    if (e < E) atomicAdd(&g_deg[ei[E + e]], 1);
}

// ---------------- scan: offsets of (deg-1), cursors, dinv ----------------
// single block, 1024 threads, contiguous chunks + Hillis-Steele block scan

__global__ void __launch_bounds__(1024, 1) k_scan(int n) {
    __shared__ int part[1024];
    int t = threadIdx.x;
    int chunk = (n + 1023) >> 10;
    int s = t * chunk;
    int e = min(s + chunk, n);
    int sum = 0;
    for (int i = s; i < e; i++) sum += g_deg[i] - 1;
    part[t] = sum;
    __syncthreads();
    #pragma unroll
    for (int off = 1; off < 1024; off <<= 1) {
        int v = (t >= off) ? part[t - off] : 0;
        __syncthreads();
        part[t] += v;
        __syncthreads();
    }
    int base = (t == 0) ? 0 : part[t - 1];
    for (int i = s; i < e; i++) {
        g_off[i] = base;
        g_cur[i] = base;
        base += g_deg[i] - 1;
        g_dinv[i] = rsqrtf((float)g_deg[i]);
    }
}

// ---------------- CSR bucket fill ----------------

__global__ void k_fill(const int* __restrict__ ei, int E) {
    int e = blockIdx.x * blockDim.x + threadIdx.x;
    if (e >= E) return;
    int src = ei[e];
    int dst = ei[E + e];
    int pos = atomicAdd(&g_cur[dst], 1);
    g_csr[pos] = src;
}

// ---------------- fused GEMM: hs = (in @ W) * dinv ----------------
// mode 0: in = X; mode 1: in = g_x2

__global__ void __launch_bounds__(256, 2)
k_gemm(const float* __restrict__ X, const float* __restrict__ W, int n, int mode)
{
    __shared__ __align__(16) float  Ws[D * D];
    __shared__ __align__(16) float4 xs[64][16];
    int t = threadIdx.x;
    const float* Xp = mode ? g_x2 : X;

    #pragma unroll
    for (int i = 0; i < 4; i++)
        ((float4*)Ws)[t + 256 * i] = ((const float4*)W)[t + 256 * i];

    int base = blockIdx.x * 64;

    #pragma unroll
    for (int r = 0; r < 4; r++) {
        int i = t + 256 * r;
        int node = base + (i >> 4);
        int k4 = i & 15;
        float4 v = make_float4(0.f, 0.f, 0.f, 0.f);
        if (node < n) v = ((const float4*)Xp)[(size_t)node * 16 + k4];
        xs[i >> 4][k4] = v;
    }
    __syncthreads();

    int j = t & 63, g = t >> 6;
    float wcol[D];
    #pragma unroll
    for (int k = 0; k < D; k++) wcol[k] = Ws[k * D + j];

    #pragma unroll
    for (int batch = 0; batch < 4; batch++) {
        int n0 = g * 16 + batch * 4;
        float acc0 = 0.f, acc1 = 0.f, acc2 = 0.f, acc3 = 0.f;
        #pragma unroll
        for (int k4 = 0; k4 < 16; k4++) {
            float4 x0 = xs[n0 + 0][k4];
            float4 x1 = xs[n0 + 1][k4];
            float4 x2 = xs[n0 + 2][k4];
            float4 x3 = xs[n0 + 3][k4];
            float w0 = wcol[4 * k4 + 0], w1 = wcol[4 * k4 + 1];
            float w2 = wcol[4 * k4 + 2], w3 = wcol[4 * k4 + 3];
            acc0 = fmaf(x0.x, w0, acc0); acc0 = fmaf(x0.y, w1, acc0);
            acc0 = fmaf(x0.z, w2, acc0); acc0 = fmaf(x0.w, w3, acc0);
            acc1 = fmaf(x1.x, w0, acc1); acc1 = fmaf(x1.y, w1, acc1);
            acc1 = fmaf(x1.z, w2, acc1); acc1 = fmaf(x1.w, w3, acc1);
            acc2 = fmaf(x2.x, w0, acc2); acc2 = fmaf(x2.y, w1, acc2);
            acc2 = fmaf(x2.z, w2, acc2); acc2 = fmaf(x2.w, w3, acc2);
            acc3 = fmaf(x3.x, w0, acc3); acc3 = fmaf(x3.y, w1, acc3);
            acc3 = fmaf(x3.z, w2, acc3); acc3 = fmaf(x3.w, w3, acc3);
        }
        float accs[4] = {acc0, acc1, acc2, acc3};
        #pragma unroll
        for (int q = 0; q < 4; q++) {
            int node = base + n0 + q;
            if (node < n)
                g_hs[(size_t)node * D + j] = accs[q] * g_dinv[node];
        }
    }
}

// ---------------- CSR aggregation + fused epilogue ----------------
// out[node] = prelu( (hs[node] + sum_{src in bucket} hs[src]) * dinv[node] + b, a )
// 16 threads per node, one float4 lane each. dstX2: write g_x2 else out.

__global__ void __launch_bounds__(256)
k_agg(const float* __restrict__ b, const float* __restrict__ a,
      float* __restrict__ out, int n, int dstX2)
{
    int tid = blockIdx.x * blockDim.x + threadIdx.x;
    int node = tid >> 4;
    if (node >= n) return;
    int q = tid & 15;

    const float4* hs4 = (const float4*)g_hs;
    float4 acc = __ldg(&hs4[(size_t)node * 16 + q]);   // self-loop

    int s  = g_off[node];
    int e2 = g_cur[node];
    #pragma unroll 4
    for (int i = s; i < e2; i++) {
        int src = g_csr[i];
        float4 v = __ldg(&hs4[(size_t)src * 16 + q]);
        acc.x += v.x; acc.y += v.y; acc.z += v.z; acc.w += v.w;
    }

    float dv = g_dinv[node];
    float4 bb = ((const float4*)b)[q];
    float4 aa = ((const float4*)a)[q];
    acc.x = acc.x * dv + bb.x; acc.x = (acc.x >= 0.f) ? acc.x : aa.x * acc.x;
    acc.y = acc.y * dv + bb.y; acc.y = (acc.y >= 0.f) ? acc.y : aa.y * acc.y;
    acc.z = acc.z * dv + bb.z; acc.z = (acc.z >= 0.f) ? acc.z : aa.z * acc.z;
    acc.w = acc.w * dv + bb.w; acc.w = (acc.w >= 0.f) ? acc.w : aa.w * acc.w;

    float4* op = dstX2 ? (float4*)g_x2 : (float4*)out;
    op[(size_t)node * 16 + q] = acc;
}

// ---------------- launch ----------------

extern "C" void kernel_launch(void* const* d_in, const int* in_sizes, int n_in,
                              void* d_out, int out_size) {
    const float* x  = (const float*)d_in[0];
    const int*   ei = (const int*)d_in[1];     // int32 (JAX x64 disabled)
    const float* W1 = (const float*)d_in[2];
    const float* b1 = (const float*)d_in[3];
    const float* a1 = (const float*)d_in[4];
    const float* W2 = (const float*)d_in[5];
    const float* b2 = (const float*)d_in[6];
    const float* a2 = (const float*)d_in[7];
    float* out = (float*)d_out;

    int n = in_sizes[0] / D;
    int E = in_sizes[1] / 2;

    int nb_n  = (n + 255) / 256;
    int nb_e  = (E + 255) / 256;
    int nb_gm = (n + 63) / 64;
    int nb_ag = (int)(((long long)n * 16 + 255) / 256);

    // CSR build + norms
    k_init_deg<<<nb_n, 256>>>(n);
    k_count   <<<nb_e, 256>>>(ei, E);
    k_scan    <<<1, 1024>>>(n);
    k_fill    <<<nb_e, 256>>>(ei, E);

    // layer 1
    k_gemm<<<nb_gm, 256>>>(x, W1, n, 0);
    k_agg <<<nb_ag, 256>>>(b1, a1, out, n, 1);   // -> g_x2

    // layer 2
    k_gemm<<<nb_gm, 256>>>(x, W2, n, 1);         // reads g_x2
    k_agg <<<nb_ag, 256>>>(b2, a2, out, n, 0);   // -> d_out
}